// round 3
// baseline (speedup 1.0000x reference)
#include <cuda_runtime.h>
#include <cstdint>

// HashGrid2D: out[i] = table[bitmix_hash(floor(pos[i].x), floor(pos[i].y))]
// HASH_BITS=19, DIM=8, CELL_SIZE=1.0
//
// inputs (metadata order): d_in[0] = positions [N,2] fp32, d_in[1] = table [2^19, 8] fp32
// output: [N, 8] fp32

#define HASH_BITS 19
#define HASH_MASK ((1u << HASH_BITS) - 1u)

__global__ __launch_bounds__(256)
void hashgrid2d_kernel(const float2* __restrict__ pos,
                       const float4* __restrict__ table,  // rows of 2x float4
                       float4* __restrict__ out,
                       int n)
{
    int i = blockIdx.x * blockDim.x + threadIdx.x;
    if (i >= n) return;

    float2 p = pos[i];

    // CELL_SIZE = 1.0 -> plain floor. Positions are in [0, 4096).
    long long ix = (long long)floorf(p.x);
    long long iy = (long long)floorf(p.y);

    // Murmur-inspired bitmix, int64 wraparound (matches jnp int64 / torch .long())
    long long h = ix;
    h ^= h >> 16;                 // arithmetic shift == jnp int64 >>
    h *= 2246822507LL;
    h ^= h >> 13;
    h += iy * 3266489909LL;
    h ^= h >> 16;

    // jnp.mod(h, 2^19) nonneg == low 19 bits (two's complement)
    unsigned idx = (unsigned)h & HASH_MASK;

    // gather one 32B row (two LDG.128), mostly L2-resident (table = 16MB)
    const float4* row = table + ((size_t)idx << 1);
    float4 lo = row[0];
    float4 hi = row[1];

    // coalesced 32B store per thread (two STG.128)
    size_t o = (size_t)i << 1;
    out[o]     = lo;
    out[o + 1] = hi;
}

extern "C" void kernel_launch(void* const* d_in, const int* in_sizes, int n_in,
                              void* d_out, int out_size)
{
    const float2* pos   = (const float2*)d_in[0];
    const float4* table = (const float4*)d_in[1];
    float4*       out   = (float4*)d_out;

    int n = in_sizes[0] / 2;  // positions has N*2 floats

    int threads = 256;
    int blocks = (n + threads - 1) / threads;
    hashgrid2d_kernel<<<blocks, threads>>>(pos, table, out, n);
}

// round 8
// speedup vs baseline: 1.1887x; 1.1887x over previous
#include <cuda_runtime.h>
#include <cstdint>

// HashGrid2D: out[i] = table[bitmix_hash(floor(pos[i].x), floor(pos[i].y))]
// HASH_BITS=19, DIM=8, CELL_SIZE=1.0
//
// Pair-cooperative gather: 2 threads per row, each loading one float4 (16B)
// of the 32B table row. Adjacent lanes hit the same 128B line inside ONE
// LDG.128 instruction -> L1 coalesces them -> 1 wavefront + 1 L2 sector per
// row instead of 2. Hash computed redundantly per pair (ALU is idle).
//
// inputs: d_in[0] = positions [N,2] fp32, d_in[1] = table [2^19, 8] fp32
// output: [N, 8] fp32

#define HASH_BITS 19
#define HASH_MASK ((1u << HASH_BITS) - 1u)

__global__ __launch_bounds__(256)
void hashgrid2d_pair_kernel(const float2* __restrict__ pos,
                            const float4* __restrict__ table,  // rows = 2x float4
                            float4* __restrict__ out,
                            int n2)                            // = 2*N
{
    int t = blockIdx.x * blockDim.x + threadIdx.x;
    if (t >= n2) return;

    int i    = t >> 1;   // position / row index
    int half = t & 1;    // which float4 of the 32B row

    float2 p = pos[i];   // pair-broadcast: both lanes of a pair read same 8B

    // CELL_SIZE = 1.0 -> plain floor. Positions in [0, 4096).
    long long ix = (long long)floorf(p.x);
    long long iy = (long long)floorf(p.y);

    // Murmur-inspired bitmix, int64 wraparound (matches jnp int64 semantics)
    long long h = ix;
    h ^= h >> 16;                 // arithmetic shift == jnp int64 >>
    h *= 2246822507LL;
    h ^= h >> 13;
    h += iy * 3266489909LL;
    h ^= h >> 16;

    // jnp.mod(h, 2^19) nonneg == low 19 bits (two's complement)
    unsigned idx = (unsigned)h & HASH_MASK;

    // one float4 of the row; pair lanes share the 128B line -> coalesced
    float4 v = table[((size_t)idx << 1) + half];

    // out[i*2 + half] == out[t] : perfectly coalesced STG.128
    out[t] = v;
}

extern "C" void kernel_launch(void* const* d_in, const int* in_sizes, int n_in,
                              void* d_out, int out_size)
{
    const float2* pos   = (const float2*)d_in[0];
    const float4* table = (const float4*)d_in[1];
    float4*       out   = (float4*)d_out;

    int n  = in_sizes[0] / 2;  // positions has N*2 floats
    int n2 = n * 2;            // 2 threads per position

    int threads = 256;
    int blocks  = (n2 + threads - 1) / threads;
    hashgrid2d_pair_kernel<<<blocks, threads>>>(pos, table, out, n2);
}

// round 9
// speedup vs baseline: 1.2625x; 1.0621x over previous
#include <cuda_runtime.h>
#include <cstdint>

// HashGrid2D: out[i] = table[bitmix_hash(floor(pos[i].x), floor(pos[i].y))]
// HASH_BITS=19, DIM=8, CELL_SIZE=1.0
//
// Pair-cooperative gather (2 threads per 32B row, one float4 each -> adjacent
// lanes coalesce into one LDG.128 wavefront + one L2 sector per row) combined
// with G=4 batching per thread: 4 independent gathers issued back-to-back to
// raise memory-level parallelism ~4x and hide the ~250cyc L2-hit latency.
//
// inputs: d_in[0] = positions [N,2] fp32, d_in[1] = table [2^19, 8] fp32
// output: [N, 8] fp32

#define HASH_BITS 19
#define HASH_MASK ((1u << HASH_BITS) - 1u)
#define G 4

__global__ __launch_bounds__(256)
void hashgrid2d_pair4_kernel(const float2* __restrict__ pos,
                             const float4* __restrict__ table,  // rows = 2x float4
                             float4* __restrict__ out,
                             int n2,                             // = 2*N slots
                             int T)                              // threads = ceil(n2/G)
{
    int t = blockIdx.x * blockDim.x + threadIdx.x;
    if (t >= T) return;

    // ---- phase 1: front-batched position loads (coalesced, pair-broadcast)
    int    s[G];
    float2 p[G];
#pragma unroll
    for (int j = 0; j < G; j++) {
        s[j] = t + j * T;                 // strided slots: coalesced per batch elem
        p[j] = (s[j] < n2) ? pos[s[j] >> 1] : make_float2(0.f, 0.f);
    }

    // ---- phase 2: hashes (int64 wraparound, matches jnp int64 semantics)
    unsigned idx[G];
#pragma unroll
    for (int j = 0; j < G; j++) {
        long long ix = (long long)floorf(p[j].x);   // CELL_SIZE = 1.0
        long long iy = (long long)floorf(p[j].y);
        long long h = ix;
        h ^= h >> 16;                               // arithmetic shift
        h *= 2246822507LL;
        h ^= h >> 13;
        h += iy * 3266489909LL;
        h ^= h >> 16;
        idx[j] = (unsigned)h & HASH_MASK;           // mod 2^19, nonneg
    }

    // ---- phase 3: 4 independent gathers in flight (the MLP payoff)
    float4 v[G];
#pragma unroll
    for (int j = 0; j < G; j++) {
        if (s[j] < n2)
            v[j] = table[((size_t)idx[j] << 1) + (s[j] & 1)];
    }

    // ---- phase 4: coalesced streaming stores
#pragma unroll
    for (int j = 0; j < G; j++) {
        if (s[j] < n2)
            out[s[j]] = v[j];
    }
}

extern "C" void kernel_launch(void* const* d_in, const int* in_sizes, int n_in,
                              void* d_out, int out_size)
{
    const float2* pos   = (const float2*)d_in[0];
    const float4* table = (const float4*)d_in[1];
    float4*       out   = (float4*)d_out;

    int n  = in_sizes[0] / 2;   // N positions
    int n2 = n * 2;             // pair slots
    int T  = (n2 + G - 1) / G;  // threads

    int threads = 256;
    int blocks  = (T + threads - 1) / threads;
    hashgrid2d_pair4_kernel<<<blocks, threads>>>(pos, table, out, n2, T);
}

// round 10
// speedup vs baseline: 1.4665x; 1.1616x over previous
#include <cuda_runtime.h>
#include <cstdint>

// HashGrid2D: out[i] = table[bitmix_hash(floor(pos[i].x), floor(pos[i].y))]
// HASH_BITS=19, DIM=8, CELL_SIZE=1.0
//
// Pair-cooperative gather (2 threads per 32B row -> 1 L1 wavefront + 1 L2
// sector per row) + G=8 batching for ~8x memory-level parallelism, streaming
// loads for positions and streaming (evict-first) stores for the output so
// the 256MB write stream doesn't evict the 16MB L2-resident table.
//
// inputs: d_in[0] = positions [N,2] fp32, d_in[1] = table [2^19, 8] fp32
// output: [N, 8] fp32

#define HASH_BITS 19
#define HASH_MASK ((1u << HASH_BITS) - 1u)
#define G 8

template<bool GUARD>
__global__ __launch_bounds__(256)
void hashgrid2d_pair8_kernel(const float2* __restrict__ pos,
                             const float4* __restrict__ table,  // rows = 2x float4
                             float4* __restrict__ out,
                             int n2,                             // = 2*N slots
                             int T)                              // threads
{
    int t = blockIdx.x * blockDim.x + threadIdx.x;
    if (GUARD && t >= T) return;

    // ---- phase 1: front-batched position loads (coalesced, pair-broadcast,
    //               streaming: read-once data)
    float2 p[G];
#pragma unroll
    for (int j = 0; j < G; j++) {
        int s = t + j * T;
        if (!GUARD || s < n2) p[j] = __ldcs(&pos[s >> 1]);
        else                  p[j] = make_float2(0.f, 0.f);
    }

    // ---- phase 2: hashes (int64 wraparound, matches jnp int64 semantics)
    unsigned idx[G];
#pragma unroll
    for (int j = 0; j < G; j++) {
        long long ix = (long long)floorf(p[j].x);   // CELL_SIZE = 1.0
        long long iy = (long long)floorf(p[j].y);
        long long h = ix;
        h ^= h >> 16;                               // arithmetic shift
        h *= 2246822507LL;
        h ^= h >> 13;
        h += iy * 3266489909LL;
        h ^= h >> 16;
        idx[j] = (unsigned)h & HASH_MASK;           // mod 2^19, nonneg
    }

    // ---- phase 3: 8 independent gathers in flight (MLP payoff; default .ca
    //               load keeps the table cached in L2)
    float4 v[G];
#pragma unroll
    for (int j = 0; j < G; j++) {
        int s = t + j * T;
        if (!GUARD || s < n2)
            v[j] = table[((size_t)idx[j] << 1) + (s & 1)];
    }

    // ---- phase 4: coalesced streaming stores (evict-first: protect table in L2)
#pragma unroll
    for (int j = 0; j < G; j++) {
        int s = t + j * T;
        if (!GUARD || s < n2)
            __stcs(&out[s], v[j]);
    }
}

extern "C" void kernel_launch(void* const* d_in, const int* in_sizes, int n_in,
                              void* d_out, int out_size)
{
    const float2* pos   = (const float2*)d_in[0];
    const float4* table = (const float4*)d_in[1];
    float4*       out   = (float4*)d_out;

    int n  = in_sizes[0] / 2;   // N positions
    int n2 = n * 2;             // pair slots
    int T  = (n2 + G - 1) / G;  // threads

    int threads = 256;
    int blocks  = (T + threads - 1) / threads;

    if (n2 % G == 0) {
        // exact tiling (N = 2^23 in this problem): no bounds checks
        hashgrid2d_pair8_kernel<false><<<blocks, threads>>>(pos, table, out, n2, T);
    } else {
        hashgrid2d_pair8_kernel<true><<<blocks, threads>>>(pos, table, out, n2, T);
    }
}